// round 11
// baseline (speedup 1.0000x reference)
#include <cuda_runtime.h>
#include <cuda_bf16.h>
#include <cstdint>

// Shapes (fixed): x (1,384,256), gamma/beta (256), Wa/Wb (32,256),
// Wo (128,1024), bo (128) -> z (1,384,384,128) fp32
//
//   kA: layernorm(x) -> a = xn.Wa^T (fp32), b = xn.Wb^T (split-bf16 rows)
//       warp-per-row, no block barriers.
//   kB: U[i][o][d] = sum_c a[i][c]*Wo[o*1024+c*32+d] (split-bf16)
//   kC: z[i][j][o] = bo[o] + sum_d U[i][o][d]*b[j][d]
//       per-i (384x32)@(32x128) GEMM via mma.sync.m16n8k16.bf16 with
//       3-term split (hi*hi + lo*hi + hi*lo); fp32 accumulation.
//       (tcgen05 is NOT available: harness PTX target is compute_103,
//        which rejects arch-accelerated instructions.)

#define L   384
#define DIM 256
#define H   32
#define OUT 128

__device__ float g_a[L * H];             // fp32 [l][h] (kB input)
__device__ uint2 g_b2[L * 16];           // split-bf16 b, 16 d-pairs per row
__device__ uint2 g_U2[L * OUT * 16];     // split-bf16 U, [i][o][dpair]

// split (x,y) fp32 pair -> {hi bf16x2, lo bf16x2}
__device__ __forceinline__ uint2 split2(float x, float y) {
    __nv_bfloat162 h = __floats2bfloat162_rn(x, y);
    float2 hf = __bfloat1622float2(h);
    __nv_bfloat162 lo = __floats2bfloat162_rn(x - hf.x, y - hf.y);
    uint2 r;
    r.x = *reinterpret_cast<unsigned*>(&h);
    r.y = *reinterpret_cast<unsigned*>(&lo);
    return r;
}

#define MMA_BF16(c, a0, a1, a2, a3, b0, b1)                                   \
    asm volatile(                                                             \
        "mma.sync.aligned.m16n8k16.row.col.f32.bf16.bf16.f32 "                \
        "{%0,%1,%2,%3}, {%4,%5,%6,%7}, {%8,%9}, {%0,%1,%2,%3};\n"             \
        : "+f"((c)[0]), "+f"((c)[1]), "+f"((c)[2]), "+f"((c)[3])              \
        : "r"(a0), "r"(a1), "r"(a2), "r"(a3), "r"(b0), "r"(b1))

// ---------------------------------------------------------------------------
// Kernel A: warp-per-row LN + GEMV. 96 blocks x 128 threads (4 warps).
// Warp w handles row l = blk*4 + w. No __syncthreads at all.
// ---------------------------------------------------------------------------
__global__ void __launch_bounds__(128) kA(
    const float* __restrict__ x, const float* __restrict__ gamma,
    const float* __restrict__ beta, const float* __restrict__ Wa,
    const float* __restrict__ Wb)
{
    const int t = threadIdx.x;
    const int lane = t & 31, w = t >> 5;
    const int l = blockIdx.x * 4 + w;

    // Load row (8 elements per lane, coalesced)
    float xv[8];
    #pragma unroll
    for (int k = 0; k < 8; k++)
        xv[k] = x[l * DIM + k * 32 + lane];

    float s = 0.f, s2 = 0.f;
    #pragma unroll
    for (int k = 0; k < 8; k++) { s += xv[k]; s2 += xv[k] * xv[k]; }
    #pragma unroll
    for (int off = 16; off; off >>= 1) {
        s  += __shfl_xor_sync(0xffffffffu, s,  off);
        s2 += __shfl_xor_sync(0xffffffffu, s2, off);
    }
    const float mu   = s * (1.0f / DIM);
    const float rstd = rsqrtf(s2 * (1.0f / DIM) - mu * mu + 1e-5f);

    float xn[8];
    #pragma unroll
    for (int k = 0; k < 8; k++)
        xn[k] = (xv[k] - mu) * rstd * gamma[k * 32 + lane]
              + beta[k * 32 + lane];

    // 64 dots of length 256, in 8 groups of 8 (independent LDG/FMA streams)
    #pragma unroll
    for (int grp = 0; grp < 8; grp++) {
        float acc[8];
        #pragma unroll
        for (int q = 0; q < 8; q++) {
            const int idx = grp * 8 + q;          // 0..31 -> a, 32..63 -> b
            const float* Wrow = ((idx < 32) ? Wa : Wb) + (idx & 31) * DIM + lane;
            float a = 0.f;
            #pragma unroll
            for (int k = 0; k < 8; k++)
                a += xn[k] * Wrow[k * 32];
            acc[q] = a;
        }
        #pragma unroll
        for (int off = 16; off; off >>= 1) {
            #pragma unroll
            for (int q = 0; q < 8; q++)
                acc[q] += __shfl_xor_sync(0xffffffffu, acc[q], off);
        }
        if (lane == 0) {
            if (grp < 4) {
                #pragma unroll
                for (int q = 0; q < 8; q++)
                    g_a[l * H + grp * 8 + q] = acc[q];
            } else {
                const int h0 = (grp - 4) * 8;
                #pragma unroll
                for (int p = 0; p < 4; p++)
                    g_b2[l * 16 + (h0 >> 1) + p] =
                        split2(acc[2 * p], acc[2 * p + 1]);
            }
        }
    }
}

// ---------------------------------------------------------------------------
// Kernel B: U[i][o][d] = sum_c a[i][c] * Wo[o*1024 + c*32 + d]
// grid (48, 16): 8 i's, 8 o's per block (one o per warp). lane = d.
// ---------------------------------------------------------------------------
__global__ void __launch_bounds__(256) kB(const float* __restrict__ Wo)
{
    const int it0 = blockIdx.x * 8;
    const int t = threadIdx.x;
    const int lane = t & 31, w = t >> 5;
    const int o = blockIdx.y * 8 + w;

    __shared__ float a_sh[8 * H];
    a_sh[t] = g_a[it0 * H + t];
    __syncthreads();

    const float* wrow = Wo + o * (H * H) + lane;
    float acc[8];
    #pragma unroll
    for (int i = 0; i < 8; i++) acc[i] = 0.f;
    #pragma unroll
    for (int c = 0; c < H; c++) {
        float wv = wrow[c * H];
        #pragma unroll
        for (int i = 0; i < 8; i++)
            acc[i] += a_sh[i * H + c] * wv;
    }
    // form d-pairs: even lane holds (d, d+1)
    #pragma unroll
    for (int i = 0; i < 8; i++) {
        float other = __shfl_xor_sync(0xffffffffu, acc[i], 1);
        if ((lane & 1) == 0) {
            g_U2[((it0 + i) * OUT + o) * 16 + (lane >> 1)] =
                split2(acc[i], other);
        }
    }
}

// ---------------------------------------------------------------------------
// Kernel C: per-i GEMM Z_i[j,o] = bo[o] + B[j,:].U_i[o,:]^T, bf16 MMA.
// grid (384, 3): one i, 128 j per block, 256 threads = 8 warps.
// (unchanged from round-9 passing version)
// ---------------------------------------------------------------------------
#define RS 20   // row stride in uint2

__global__ void __launch_bounds__(256) kC(
    const float* __restrict__ bo, float* __restrict__ z)
{
    __shared__ uint2 Ub[OUT * RS];   // 20480 B
    __shared__ uint2 Bs[128 * RS];   // 20480 B

    const int i     = blockIdx.x;
    const int jbase = blockIdx.y * 128;
    const int t = threadIdx.x;
    const int lane = t & 31, w = t >> 5;
    const int g = lane >> 2, t4 = lane & 3;

    // Copy-in: each matrix is 128 rows x 8 uint4 = 1024 uint4.
    {
        const uint4* Ug = (const uint4*)(g_U2 + (size_t)i * OUT * 16);
        const uint4* Bg = (const uint4*)(g_b2 + (size_t)jbase * 16);
        #pragma unroll
        for (int it = 0; it < 4; it++) {
            int idx = t + it * 256;          // 0..1023
            int row = idx >> 3, q = idx & 7; // 8 uint4 per row
            *(uint4*)(Ub + row * RS + q * 2) = Ug[idx];
            *(uint4*)(Bs + row * RS + q * 2) = Bg[idx];
        }
    }
    __syncthreads();

    float acc[16][4];
    #pragma unroll
    for (int ot = 0; ot < 16; ot++)
        #pragma unroll
        for (int c = 0; c < 4; c++) acc[ot][c] = 0.f;

    const int jr = w * 16;

    #pragma unroll
    for (int kk = 0; kk < 2; kk++) {
        const uint2* ap = Bs + (jr + g) * RS + kk * 8 + t4;
        uint2 A00 = ap[0];
        uint2 A01 = ap[4];
        uint2 A10 = ap[8 * RS];
        uint2 A11 = ap[8 * RS + 4];

        const uint2* bp0 = Ub + g * RS + kk * 8 + t4;
        #pragma unroll
        for (int ot = 0; ot < 16; ot++) {
            const uint2* bp = bp0 + ot * 8 * RS;
            uint2 B0 = bp[0];
            uint2 B1 = bp[4];
            MMA_BF16(acc[ot], A00.x, A10.x, A01.x, A11.x, B0.x, B1.x); // hh
            MMA_BF16(acc[ot], A00.y, A10.y, A01.y, A11.y, B0.x, B1.x); // lh
            MMA_BF16(acc[ot], A00.x, A10.x, A01.x, A11.x, B0.y, B1.y); // hl
        }
    }

    const float2* bo2 = (const float2*)bo;
    size_t zrow = ((size_t)i * L + jbase + jr + g) * OUT;
    #pragma unroll
    for (int ot = 0; ot < 16; ot++) {
        int o = ot * 8 + 2 * t4;
        float2 bb = bo2[o >> 1];
        float2 v0 = make_float2(acc[ot][0] + bb.x, acc[ot][1] + bb.y);
        float2 v1 = make_float2(acc[ot][2] + bb.x, acc[ot][3] + bb.y);
        *(float2*)(z + zrow + o)           = v0;
        *(float2*)(z + zrow + 8 * OUT + o) = v1;
    }
}

// ---------------------------------------------------------------------------
extern "C" void kernel_launch(void* const* d_in, const int* in_sizes, int n_in,
                              void* d_out, int out_size)
{
    const float* x     = (const float*)d_in[0];
    const float* gamma = (const float*)d_in[1];
    const float* beta  = (const float*)d_in[2];
    const float* Wa    = (const float*)d_in[3];
    const float* Wb    = (const float*)d_in[4];
    const float* Wo    = (const float*)d_in[5];
    const float* bo    = (const float*)d_in[6];
    float* z = (float*)d_out;

    kA<<<96, 128>>>(x, gamma, beta, Wa, Wb);
    kB<<<dim3(48, 16), 256>>>(Wo);
    kC<<<dim3(L, 3), 256>>>(bo, z);
}

// round 12
// speedup vs baseline: 1.4160x; 1.4160x over previous
#include <cuda_runtime.h>
#include <cuda_bf16.h>
#include <cstdint>

// Shapes (fixed): x (1,384,256), gamma/beta (256), Wa/Wb (32,256),
// Wo (128,1024), bo (128) -> z (1,384,384,128) fp32
//
//   kA: layernorm(x) -> a = xn.Wa^T (fp32), b = xn.Wb^T (split-bf16)
//       grid (384,2): y=0 -> a-half, y=1 -> b-half (LN recomputed).
//   kB: U[i][o][d] = sum_c a[i][c]*Wo[o*1024+c*32+d] (split-bf16)
//   kC: z[i][j][o] = bo[o] + sum_d U[i][o][d]*b[j][d]
//       per-i (384x32)@(32x128) GEMM via mma.sync.m16n8k16.bf16 with
//       3-term split (hi*hi + lo*hi + hi*lo); fp32 accumulation.
//       (tcgen05 unavailable: harness PTX target is compute_103.)

#define L   384
#define DIM 256
#define H   32
#define OUT 128

__device__ float g_a[L * H];             // fp32 [l][h] (kB input)
__device__ uint2 g_b2[L * 16];           // split-bf16 b, 16 d-pairs per row
__device__ uint2 g_U2[L * OUT * 16];     // split-bf16 U, [i][o][dpair]

// split (x,y) fp32 pair -> {hi bf16x2, lo bf16x2}
__device__ __forceinline__ uint2 split2(float x, float y) {
    __nv_bfloat162 h = __floats2bfloat162_rn(x, y);
    float2 hf = __bfloat1622float2(h);
    __nv_bfloat162 lo = __floats2bfloat162_rn(x - hf.x, y - hf.y);
    uint2 r;
    r.x = *reinterpret_cast<unsigned*>(&h);
    r.y = *reinterpret_cast<unsigned*>(&lo);
    return r;
}

#define MMA_BF16(c, a0, a1, a2, a3, b0, b1)                                   \
    asm volatile(                                                             \
        "mma.sync.aligned.m16n8k16.row.col.f32.bf16.bf16.f32 "                \
        "{%0,%1,%2,%3}, {%4,%5,%6,%7}, {%8,%9}, {%0,%1,%2,%3};\n"             \
        : "+f"((c)[0]), "+f"((c)[1]), "+f"((c)[2]), "+f"((c)[3])              \
        : "r"(a0), "r"(a1), "r"(a2), "r"(a3), "r"(b0), "r"(b1))

// ---------------------------------------------------------------------------
// Kernel A: layernorm + one 32-row GEMV half per block. grid (384, 2).
// y=0: a = xn.Wa^T (fp32 out). y=1: b = xn.Wb^T (split-bf16 out).
// Warp w computes 4 dots (idx = 4w..4w+3); coalesced W reads.
// ---------------------------------------------------------------------------
__global__ void __launch_bounds__(256) kA(
    const float* __restrict__ x, const float* __restrict__ gamma,
    const float* __restrict__ beta, const float* __restrict__ Wa,
    const float* __restrict__ Wb)
{
    const int l  = blockIdx.x;
    const int half = blockIdx.y;          // 0 -> a, 1 -> b
    const int t = threadIdx.x;
    const int lane = t & 31, w = t >> 5;

    __shared__ float xn_sh[DIM];
    __shared__ float red[16];
    __shared__ float mu_s, rstd_s;

    float v = x[l * DIM + t];

    float s = v, s2 = v * v;
    #pragma unroll
    for (int off = 16; off; off >>= 1) {
        s  += __shfl_down_sync(0xffffffffu, s,  off);
        s2 += __shfl_down_sync(0xffffffffu, s2, off);
    }
    if (lane == 0) { red[w] = s; red[8 + w] = s2; }
    __syncthreads();
    if (t == 0) {
        float S = 0.f, S2 = 0.f;
        #pragma unroll
        for (int k = 0; k < 8; k++) { S += red[k]; S2 += red[8 + k]; }
        float mu  = S * (1.0f / DIM);
        float var = S2 * (1.0f / DIM) - mu * mu;
        mu_s   = mu;
        rstd_s = rsqrtf(var + 1e-5f);
    }
    __syncthreads();

    xn_sh[t] = (v - mu_s) * rstd_s * gamma[t] + beta[t];
    __syncthreads();

    const int h0 = w * 4;
    const float* M = (half == 0 ? Wa : Wb) + h0 * DIM + lane;

    float acc[4];
    #pragma unroll
    for (int q = 0; q < 4; q++) acc[q] = 0.f;

    #pragma unroll
    for (int k = 0; k < 8; k++) {
        float xv = xn_sh[k * 32 + lane];
        #pragma unroll
        for (int q = 0; q < 4; q++)
            acc[q] += xv * M[q * DIM + k * 32];
    }

    #pragma unroll
    for (int off = 16; off; off >>= 1) {
        #pragma unroll
        for (int q = 0; q < 4; q++)
            acc[q] += __shfl_xor_sync(0xffffffffu, acc[q], off);
    }

    if (lane == 0) {
        if (half == 0) {
            #pragma unroll
            for (int q = 0; q < 4; q++)
                g_a[l * H + h0 + q] = acc[q];
        } else {
            g_b2[l * 16 + (h0 >> 1)]     = split2(acc[0], acc[1]);
            g_b2[l * 16 + (h0 >> 1) + 1] = split2(acc[2], acc[3]);
        }
    }
}

// ---------------------------------------------------------------------------
// Kernel B: U[i][o][d] = sum_c a[i][c] * Wo[o*1024 + c*32 + d]
// grid (48, 16): 8 i's, 8 o's per block (one o per warp). lane = d.
// ---------------------------------------------------------------------------
__global__ void __launch_bounds__(256) kB(const float* __restrict__ Wo)
{
    const int it0 = blockIdx.x * 8;
    const int t = threadIdx.x;
    const int lane = t & 31, w = t >> 5;
    const int o = blockIdx.y * 8 + w;

    __shared__ float a_sh[8 * H];
    a_sh[t] = g_a[it0 * H + t];
    __syncthreads();

    const float* wrow = Wo + o * (H * H) + lane;
    float acc[8];
    #pragma unroll
    for (int i = 0; i < 8; i++) acc[i] = 0.f;
    #pragma unroll
    for (int c = 0; c < H; c++) {
        float wv = wrow[c * H];
        #pragma unroll
        for (int i = 0; i < 8; i++)
            acc[i] += a_sh[i * H + c] * wv;
    }
    // form d-pairs: even lane holds (d, d+1)
    #pragma unroll
    for (int i = 0; i < 8; i++) {
        float other = __shfl_xor_sync(0xffffffffu, acc[i], 1);
        if ((lane & 1) == 0) {
            g_U2[((it0 + i) * OUT + o) * 16 + (lane >> 1)] =
                split2(acc[i], other);
        }
    }
}

// ---------------------------------------------------------------------------
// Kernel C: per-i GEMM Z_i[j,o] = bo[o] + B[j,:].U_i[o,:]^T, bf16 MMA.
// grid (384, 3): one i, 128 j per block, 256 threads = 8 warps.
// (R9 structure; z stores are streaming (.cs) — z is write-once, keep U
//  resident in L2 for its 3x re-reads.)
// ---------------------------------------------------------------------------
#define RS 20   // row stride in uint2

__global__ void __launch_bounds__(256) kC(
    const float* __restrict__ bo, float* __restrict__ z)
{
    __shared__ uint2 Ub[OUT * RS];   // 20480 B
    __shared__ uint2 Bs[128 * RS];   // 20480 B

    const int i     = blockIdx.x;
    const int jbase = blockIdx.y * 128;
    const int t = threadIdx.x;
    const int lane = t & 31, w = t >> 5;
    const int g = lane >> 2, t4 = lane & 3;

    // Copy-in: each matrix is 128 rows x 8 uint4 = 1024 uint4.
    {
        const uint4* Ug = (const uint4*)(g_U2 + (size_t)i * OUT * 16);
        const uint4* Bg = (const uint4*)(g_b2 + (size_t)jbase * 16);
        #pragma unroll
        for (int it = 0; it < 4; it++) {
            int idx = t + it * 256;          // 0..1023
            int row = idx >> 3, q = idx & 7; // 8 uint4 per row
            *(uint4*)(Ub + row * RS + q * 2) = Ug[idx];
            *(uint4*)(Bs + row * RS + q * 2) = Bg[idx];
        }
    }
    __syncthreads();

    float acc[16][4];
    #pragma unroll
    for (int ot = 0; ot < 16; ot++)
        #pragma unroll
        for (int c = 0; c < 4; c++) acc[ot][c] = 0.f;

    const int jr = w * 16;

    #pragma unroll
    for (int kk = 0; kk < 2; kk++) {
        const uint2* ap = Bs + (jr + g) * RS + kk * 8 + t4;
        uint2 A00 = ap[0];
        uint2 A01 = ap[4];
        uint2 A10 = ap[8 * RS];
        uint2 A11 = ap[8 * RS + 4];

        const uint2* bp0 = Ub + g * RS + kk * 8 + t4;
        #pragma unroll
        for (int ot = 0; ot < 16; ot++) {
            const uint2* bp = bp0 + ot * 8 * RS;
            uint2 B0 = bp[0];
            uint2 B1 = bp[4];
            MMA_BF16(acc[ot], A00.x, A10.x, A01.x, A11.x, B0.x, B1.x); // hh
            MMA_BF16(acc[ot], A00.y, A10.y, A01.y, A11.y, B0.x, B1.x); // lh
            MMA_BF16(acc[ot], A00.x, A10.x, A01.x, A11.x, B0.y, B1.y); // hl
        }
    }

    const float2* bo2 = (const float2*)bo;
    size_t zrow = ((size_t)i * L + jbase + jr + g) * OUT;
    #pragma unroll
    for (int ot = 0; ot < 16; ot++) {
        int o = ot * 8 + 2 * t4;
        float2 bb = bo2[o >> 1];
        float2 v0 = make_float2(acc[ot][0] + bb.x, acc[ot][1] + bb.y);
        float2 v1 = make_float2(acc[ot][2] + bb.x, acc[ot][3] + bb.y);
        __stcs((float2*)(z + zrow + o),           v0);
        __stcs((float2*)(z + zrow + 8 * OUT + o), v1);
    }
}

// ---------------------------------------------------------------------------
extern "C" void kernel_launch(void* const* d_in, const int* in_sizes, int n_in,
                              void* d_out, int out_size)
{
    const float* x     = (const float*)d_in[0];
    const float* gamma = (const float*)d_in[1];
    const float* beta  = (const float*)d_in[2];
    const float* Wa    = (const float*)d_in[3];
    const float* Wb    = (const float*)d_in[4];
    const float* Wo    = (const float*)d_in[5];
    const float* bo    = (const float*)d_in[6];
    float* z = (float*)d_out;

    kA<<<dim3(L, 2), 256>>>(x, gamma, beta, Wa, Wb);
    kB<<<dim3(48, 16), 256>>>(Wo);
    kC<<<dim3(L, 3), 256>>>(bo, z);
}

// round 13
// speedup vs baseline: 1.5147x; 1.0697x over previous
#include <cuda_runtime.h>
#include <cuda_fp16.h>
#include <cstdint>

// Shapes (fixed): x (1,384,256), gamma/beta (256), Wa/Wb (32,256),
// Wo (128,1024), bo (128) -> z (1,384,384,128) fp32
//
//   kA: layernorm(x) -> a = xn.Wa^T (fp32), b = xn.Wb^T (fp16 2-term rows)
//   kB: U[i][o][d] = sum_c a[i][c]*Wo[o*1024+c*32+d] (fp16 2-term rows)
//   kC: z[i][j][o] = bo[o] + sum_d U[i][o][d]*b[j][d]
//       per-i GEMM via mma.sync.m16n8k16.f16.f32-acc, single K=64 pass:
//       slots 0..31  : hib  x hiU
//       slots 32..63 : (hib/2048) x (loU*2048)   == hib x loU exactly
//       => z' = hib . U  (dropped eps_b . U ~ 3e-4 global rel, < 1e-3)
//   (tcgen05 unavailable: harness PTX target is compute_103.)
//
// Row format (128 B = 32 uint): words 0..15 = fp16x2 "hi" pairs,
// words 16..31 = fp16x2 "lo/scaled" pairs.

#define L   384
#define DIM 256
#define H   32
#define OUT 128

__device__ float    g_a [L * H];          // fp32 [l][h] (kB input)
__device__ unsigned g_bh[L * 32];         // b rows: [hib | hib/2048]
__device__ unsigned g_Uh[L * OUT * 32];   // U rows: [hiU | loU*2048]

#define MMA_F16(c, a0, a1, a2, a3, b0, b1)                                    \
    asm volatile(                                                             \
        "mma.sync.aligned.m16n8k16.row.col.f32.f16.f16.f32 "                  \
        "{%0,%1,%2,%3}, {%4,%5,%6,%7}, {%8,%9}, {%0,%1,%2,%3};\n"             \
        : "+f"((c)[0]), "+f"((c)[1]), "+f"((c)[2]), "+f"((c)[3])              \
        : "r"(a0), "r"(a1), "r"(a2), "r"(a3), "r"(b0), "r"(b1))

__device__ __forceinline__ unsigned h2u(__half2 h) {
    return *reinterpret_cast<unsigned*>(&h);
}

// ---------------------------------------------------------------------------
// Kernel A: layernorm + one 32-row GEMV half per block. grid (384, 2).
// y=0: a = xn.Wa^T (fp32 out). y=1: b = xn.Wb^T (fp16 2-term out).
// Warp w computes 4 dots (idx = 4w..4w+3); coalesced W reads.
// ---------------------------------------------------------------------------
__global__ void __launch_bounds__(256) kA(
    const float* __restrict__ x, const float* __restrict__ gamma,
    const float* __restrict__ beta, const float* __restrict__ Wa,
    const float* __restrict__ Wb)
{
    const int l    = blockIdx.x;
    const int half = blockIdx.y;          // 0 -> a, 1 -> b
    const int t = threadIdx.x;
    const int lane = t & 31, w = t >> 5;

    __shared__ float xn_sh[DIM];
    __shared__ float red[16];
    __shared__ float mu_s, rstd_s;

    float v = x[l * DIM + t];

    float s = v, s2 = v * v;
    #pragma unroll
    for (int off = 16; off; off >>= 1) {
        s  += __shfl_down_sync(0xffffffffu, s,  off);
        s2 += __shfl_down_sync(0xffffffffu, s2, off);
    }
    if (lane == 0) { red[w] = s; red[8 + w] = s2; }
    __syncthreads();
    if (t == 0) {
        float S = 0.f, S2 = 0.f;
        #pragma unroll
        for (int k = 0; k < 8; k++) { S += red[k]; S2 += red[8 + k]; }
        float mu  = S * (1.0f / DIM);
        float var = S2 * (1.0f / DIM) - mu * mu;
        mu_s   = mu;
        rstd_s = rsqrtf(var + 1e-5f);
    }
    __syncthreads();

    xn_sh[t] = (v - mu_s) * rstd_s * gamma[t] + beta[t];
    __syncthreads();

    const int h0 = w * 4;
    const float* M = (half == 0 ? Wa : Wb) + h0 * DIM + lane;

    float acc[4];
    #pragma unroll
    for (int q = 0; q < 4; q++) acc[q] = 0.f;

    #pragma unroll
    for (int k = 0; k < 8; k++) {
        float xv = xn_sh[k * 32 + lane];
        #pragma unroll
        for (int q = 0; q < 4; q++)
            acc[q] += xv * M[q * DIM + k * 32];
    }

    #pragma unroll
    for (int off = 16; off; off >>= 1) {
        #pragma unroll
        for (int q = 0; q < 4; q++)
            acc[q] += __shfl_xor_sync(0xffffffffu, acc[q], off);
    }

    if (lane == 0) {
        if (half == 0) {
            #pragma unroll
            for (int q = 0; q < 4; q++)
                g_a[l * H + h0 + q] = acc[q];
        } else {
            unsigned* bp = g_bh + l * 32;
            const float inv = 1.0f / 2048.0f;
            bp[2 * w]          = h2u(__floats2half2_rn(acc[0], acc[1]));
            bp[2 * w + 1]      = h2u(__floats2half2_rn(acc[2], acc[3]));
            bp[16 + 2 * w]     = h2u(__floats2half2_rn(acc[0] * inv, acc[1] * inv));
            bp[16 + 2 * w + 1] = h2u(__floats2half2_rn(acc[2] * inv, acc[3] * inv));
        }
    }
}

// ---------------------------------------------------------------------------
// Kernel B: U[i][o][d] = sum_c a[i][c] * Wo[o*1024 + c*32 + d]
// grid (48, 16): 8 i's, 8 o's per block (one o per warp). lane = d.
// Output rows: [fp16(U) pairs | fp16((U-hi)*2048) pairs].
// ---------------------------------------------------------------------------
__global__ void __launch_bounds__(256) kB(const float* __restrict__ Wo)
{
    const int it0 = blockIdx.x * 8;
    const int t = threadIdx.x;
    const int lane = t & 31, w = t >> 5;
    const int o = blockIdx.y * 8 + w;

    __shared__ float a_sh[8 * H];
    a_sh[t] = g_a[it0 * H + t];
    __syncthreads();

    const float* wrow = Wo + o * (H * H) + lane;
    float acc[8];
    #pragma unroll
    for (int i = 0; i < 8; i++) acc[i] = 0.f;
    #pragma unroll
    for (int c = 0; c < H; c++) {
        float wv = wrow[c * H];
        #pragma unroll
        for (int i = 0; i < 8; i++)
            acc[i] += a_sh[i * H + c] * wv;
    }

    #pragma unroll
    for (int i = 0; i < 8; i++) {
        float other = __shfl_xor_sync(0xffffffffu, acc[i], 1);
        if ((lane & 1) == 0) {
            float ux = acc[i], uy = other;
            __half2 hi = __floats2half2_rn(ux, uy);
            float2 hf = __half22float2(hi);
            __half2 lo = __floats2half2_rn((ux - hf.x) * 2048.0f,
                                           (uy - hf.y) * 2048.0f);
            unsigned* up = g_Uh + ((size_t)(it0 + i) * OUT + o) * 32;
            int p = lane >> 1;
            up[p]      = h2u(hi);
            up[16 + p] = h2u(lo);
        }
    }
}

// ---------------------------------------------------------------------------
// Kernel C: per-i GEMM Z_i[j,o] = bo[o] + B[j,:].U_i[o,:]^T, fp16 MMA.
// grid (384, 3): one i, 128 j per block, 256 threads = 8 warps.
// K=64 single pass (4 k16 steps): slots 0..31 hi*hi, 32..63 scaled lo*hi.
// smem rows: 32 data words + 4 pad = stride 36 (conflict-free LDS.32:
// per warp bank = (4g + t4) % 32, all distinct).
// ---------------------------------------------------------------------------
#define RS 36   // row stride in uint (words)

__global__ void __launch_bounds__(256) kC(
    const float* __restrict__ bo, float* __restrict__ z)
{
    __shared__ unsigned Ub[OUT * RS];   // 18432 B
    __shared__ unsigned Bs[128 * RS];   // 18432 B

    const int i     = blockIdx.x;
    const int jbase = blockIdx.y * 128;
    const int t = threadIdx.x;
    const int lane = t & 31, w = t >> 5;
    const int g = lane >> 2, t4 = lane & 3;

    // Copy-in: each matrix is 128 rows x 8 uint4 = 1024 uint4.
    {
        const uint4* Ug = (const uint4*)(g_Uh + (size_t)i * OUT * 32);
        const uint4* Bg = (const uint4*)(g_bh + (size_t)jbase * 32);
        #pragma unroll
        for (int it = 0; it < 4; it++) {
            int idx = t + it * 256;          // 0..1023
            int row = idx >> 3, q = idx & 7; // 8 uint4 per row
            *(uint4*)(Ub + row * RS + q * 4) = Ug[idx];
            *(uint4*)(Bs + row * RS + q * 4) = Bg[idx];
        }
    }
    __syncthreads();

    float acc[16][4];
    #pragma unroll
    for (int ot = 0; ot < 16; ot++)
        #pragma unroll
        for (int c = 0; c < 4; c++) acc[ot][c] = 0.f;

    const int jr = w * 16;

    #pragma unroll
    for (int kk = 0; kk < 4; kk++) {
        const unsigned* ar = Bs + (jr + g) * RS + kk * 8 + t4;
        unsigned A0 = ar[0];
        unsigned A2 = ar[4];
        unsigned A1 = ar[8 * RS];
        unsigned A3 = ar[8 * RS + 4];

        const unsigned* br0 = Ub + g * RS + kk * 8 + t4;
        #pragma unroll
        for (int ot = 0; ot < 16; ot++) {
            const unsigned* br = br0 + ot * 8 * RS;
            unsigned B0 = br[0];
            unsigned B1 = br[4];
            MMA_F16(acc[ot], A0, A1, A2, A3, B0, B1);
        }
    }

    const float2* bo2 = (const float2*)bo;
    size_t zrow = ((size_t)i * L + jbase + jr + g) * OUT;
    #pragma unroll
    for (int ot = 0; ot < 16; ot++) {
        int o = ot * 8 + 2 * t4;
        float2 bb = bo2[o >> 1];
        float2 v0 = make_float2(acc[ot][0] + bb.x, acc[ot][1] + bb.y);
        float2 v1 = make_float2(acc[ot][2] + bb.x, acc[ot][3] + bb.y);
        __stcs((float2*)(z + zrow + o),           v0);
        __stcs((float2*)(z + zrow + 8 * OUT + o), v1);
    }
}

// ---------------------------------------------------------------------------
extern "C" void kernel_launch(void* const* d_in, const int* in_sizes, int n_in,
                              void* d_out, int out_size)
{
    const float* x     = (const float*)d_in[0];
    const float* gamma = (const float*)d_in[1];
    const float* beta  = (const float*)d_in[2];
    const float* Wa    = (const float*)d_in[3];
    const float* Wb    = (const float*)d_in[4];
    const float* Wo    = (const float*)d_in[5];
    const float* bo    = (const float*)d_in[6];
    float* z = (float*)d_out;

    kA<<<dim3(L, 2), 256>>>(x, gamma, beta, Wa, Wb);
    kB<<<dim3(48, 16), 256>>>(Wo);
    kC<<<dim3(L, 3), 256>>>(bo, z);
}